// round 8
// baseline (speedup 1.0000x reference)
#include <cuda_runtime.h>
#include <stdint.h>

// Problem constants (from reference)
#define B_      16
#define NLINES  200
#define CFEAT   64
#define HIMG    256
#define WIMG    256
#define LLEN    64
#define NBINS   32
#define EPS_    1e-5f

// Output element offsets (flattened concatenation, float32)
#define O_NORM   0
#define O_CIMG   6400
#define O_CBODY  12800
#define O_PF     22400
#define O_PB     227200
#define O_VALID  432000
#define O_AMP    435200
#define O_SLOPE  438400
#define O_FEAT   441600

// Non-contracted IEEE ops: replicate XLA's per-HLO-op rounding exactly.
// (nvcc will NOT fuse these into FFMA.)
__device__ __forceinline__ float mulrn(float a, float b) { return __fmul_rn(a, b); }
__device__ __forceinline__ float addrn(float a, float b) { return __fadd_rn(a, b); }
__device__ __forceinline__ float subrn(float a, float b) { return __fsub_rn(a, b); }
__device__ __forceinline__ float divrn(float a, float b) { return __fdiv_rn(a, b); }

// einsum 'bnj,bij->bni' reduction: (((0 + x0*r0) + x1*r1) + x2*r2)
__device__ __forceinline__ float dot3rn(float x0, float x1, float x2,
                                        float r0, float r1, float r2) {
    return addrn(addrn(mulrn(x0, r0), mulrn(x1, r1)), mulrn(x2, r2));
}

__global__ __launch_bounds__(256, 4)
void contour_kernel(const float* __restrict__ image,
                    const float* __restrict__ feature,
                    const float* __restrict__ pose,
                    const float* __restrict__ cam,
                    const float* __restrict__ tv,
                    const float* __restrict__ fore,
                    const float* __restrict__ back,
                    float* __restrict__ out)
{
    const int line = blockIdx.x;                 // 0 .. B*NLINES-1
    const int b = line / NLINES;
    const int n = line - b * NLINES;
    const int tid = threadIdx.x;
    const int l  = tid & (LLEN - 1);             // point index 0..63
    const int cg = tid >> 6;                     // channel group 0..3 (16 ch each)

    // ---- per-line setup ----
    const float* P = pose + b * 12;
    const float* C = cam  + b * 6;
    const float* T = tv   + (size_t)line * 8;

    const float c0 = T[0], c1 = T[1], c2 = T[2];
    const float m0 = T[3], m1 = T[4], m2 = T[5];
    const float fgd = T[6], bgd = T[7];

    // centers_in_view = einsum + t (separate add); normals_in_view = einsum
    const float civ0 = addrn(dot3rn(c0, c1, c2, P[0], P[1], P[2]), P[9]);
    const float civ1 = addrn(dot3rn(c0, c1, c2, P[3], P[4], P[5]), P[10]);
    const float z    = addrn(dot3rn(c0, c1, c2, P[6], P[7], P[8]), P[11]);
    const float niv0 = dot3rn(m0, m1, m2, P[0], P[1], P[2]);
    const float niv1 = dot3rn(m0, m1, m2, P[3], P[4], P[5]);

    const float sw = C[0], sh = C[1], fx = C[2], fy = C[3], ccx = C[4], ccy = C[5];

    // p2d = civ / max(z, 1e-4); centers_in_image = p2d * f + c (mul, then add)
    const float zm = fmaxf(z, 1e-4f);
    const float cix = addrn(mulrn(divrn(civ0, zm), fx), ccx);
    const float ciy = addrn(mulrn(divrn(civ1, zm), fy), ccy);

    const bool valid1 = (z > 1e-4f);
    const bool inb = (cix >= 0.f) && (cix <= subrn(sw, 1.f)) &&
                     (ciy >= 0.f) && (ciy <= subrn(sh, 1.f));
    const bool cvalid = valid1 && inb;

    // normals_in_image = n2 / max(||n2||, 1e-12)
    const float nn = __fsqrt_rn(addrn(mulrn(niv0, niv0), mulrn(niv1, niv1)));
    const float dn = fmaxf(nn, 1e-12f);
    const float nix = divrn(niv0, dn);
    const float niy = divrn(niv1, dn);

    // continuous distance: (dist * f0) / z
    const float curfg = divrn(mulrn(fgd, fx), z);
    const float curbg = divrn(mulrn(bgd, fx), z);
    const float cd = fminf(curfg, curbg);
    bool vdl = (cd >= 6.0f) && cvalid;

    // endpoint in-bounds checks (points at l=0 and l=63), replicated arithmetic
    {
        const float p0x = addrn(cix, mulrn(-31.5f, nix));
        const float p0y = addrn(ciy, mulrn(-31.5f, niy));
        const float p1x = addrn(cix, mulrn( 31.5f, nix));
        const float p1y = addrn(ciy, mulrn( 31.5f, niy));
        vdl = vdl && (p0x >= 0.f) && (p0x < 256.f) && (p0y >= 0.f) && (p0y < 256.f)
                  && (p1x >= 0.f) && (p1x < 256.f) && (p1y >= 0.f) && (p1y < 256.f);
    }

    if (tid == 0) {
        out[O_NORM  + line * 2 + 0] = nix;
        out[O_NORM  + line * 2 + 1] = niy;
        out[O_CIMG  + line * 2 + 0] = cix;
        out[O_CIMG  + line * 2 + 1] = ciy;
        out[O_CBODY + line * 3 + 0] = c0;
        out[O_CBODY + line * 3 + 1] = c1;
        out[O_CBODY + line * 3 + 2] = c2;
        out[O_VALID + line] = vdl ? 1.0f : 0.0f;
        out[O_AMP   + line] = 0.43f;
        out[O_SLOPE + line] = 0.5f;
    }

    // ---- per-point sample coordinates: exact replication (no FMA) ----
    const float step = (float)l - 31.5f;                     // exact
    const float px = addrn(cix, mulrn(step, nix));           // mul, then add
    const float py = addrn(ciy, mulrn(step, niy));

    // grid = p/W*2 - 1; unnorm: ((g+1)*W - 1)*0.5  (each op separate, IEEE)
    const float gx = subrn(mulrn(divrn(px, 256.0f), 2.0f), 1.0f);
    const float gy = subrn(mulrn(divrn(py, 256.0f), 2.0f), 1.0f);
    const float xs = mulrn(subrn(mulrn(addrn(gx, 1.0f), 256.0f), 1.0f), 0.5f);
    const float ys = mulrn(subrn(mulrn(addrn(gy, 1.0f), 256.0f), 1.0f), 0.5f);

    // ---- pf/pb (nearest sample on image + histogram), cg==0 only ----
    if (cg == 0) {
        const int xi = (int)rintf(xs);     // round-half-even == jnp.round
        const int yi = (int)rintf(ys);
        const bool v = (xi >= 0) && (xi < WIMG) && (yi >= 0) && (yi < HIMG);
        const int xc = min(max(xi, 0), WIMG - 1);
        const int yc = min(max(yi, 0), HIMG - 1);
        const float* ib = image + (size_t)b * 3 * HIMG * WIMG + (size_t)yc * WIMG + xc;
        const float r  = v ? __ldg(ib)                   : 0.0f;
        const float g  = v ? __ldg(ib + HIMG * WIMG)     : 0.0f;
        const float bl = v ? __ldg(ib + 2 * HIMG * WIMG) : 0.0f;
        // r*32 is an exact fp op (power of 2); truncation matches astype(int32)
        const int b0 = min(max((int)(r  * (float)NBINS), 0), NBINS - 1);
        const int b1 = min(max((int)(g  * (float)NBINS), 0), NBINS - 1);
        const int b2 = min(max((int)(bl * (float)NBINS), 0), NBINS - 1);
        const int hidx = (b0 * NBINS + b1) * NBINS + b2;
        float pfv = __ldg(fore + (size_t)b * NBINS * NBINS * NBINS + hidx);
        float pbv = __ldg(back + (size_t)b * NBINS * NBINS * NBINS + hidx);
        if (pfv < EPS_ && pbv < EPS_) { pfv = EPS_; pbv = EPS_; }
        const float psum = addrn(pfv, pbv);
        __stcs(&out[O_PF + (size_t)line * LLEN + l], divrn(pfv, psum));
        __stcs(&out[O_PB + (size_t)line * LLEN + l], divrn(pbv, psum));
    }

    // ---- bilinear feature sampling: 16 channels per thread ----
    // (continuous in xs/ys — fast FMA path is numerically safe here)
    const float x0f = floorf(xs);
    const float y0f = floorf(ys);
    const float wx1 = xs - x0f;
    const float wy1 = ys - y0f;
    const float wx0 = 1.0f - wx1;
    const float wy0 = 1.0f - wy1;
    const int x0 = (int)x0f, y0 = (int)y0f;
    const int x1 = x0 + 1,   y1 = y0 + 1;
    const bool vx0 = (x0 >= 0) && (x0 < WIMG);
    const bool vx1 = (x1 >= 0) && (x1 < WIMG);
    const bool vy0 = (y0 >= 0) && (y0 < HIMG);
    const bool vy1 = (y1 >= 0) && (y1 < HIMG);
    const int x0c = min(max(x0, 0), WIMG - 1);
    const int x1c = min(max(x1, 0), WIMG - 1);
    const int y0c = min(max(y0, 0), HIMG - 1);
    const int y1c = min(max(y1, 0), HIMG - 1);

    // reference accumulation order: (x0,y0), (x0,y1), (x1,y0), (x1,y1)
    const float w00 = (vx0 && vy0) ? wx0 * wy0 : 0.0f;
    const float w01 = (vx0 && vy1) ? wx0 * wy1 : 0.0f;
    const float w10 = (vx1 && vy0) ? wx1 * wy0 : 0.0f;
    const float w11 = (vx1 && vy1) ? wx1 * wy1 : 0.0f;

    const int o00 = y0c * WIMG + x0c;
    const int o01 = y1c * WIMG + x0c;
    const int o10 = y0c * WIMG + x1c;
    const int o11 = y1c * WIMG + x1c;

    const size_t plane = (size_t)HIMG * WIMG;                 // 65536
    const float* fb = feature + ((size_t)b * CFEAT + (size_t)cg * 16) * plane;
    float* ob = out + O_FEAT + (((size_t)b * CFEAT + (size_t)cg * 16) * NLINES + n) * LLEN + l;

    // Batches of 4 channels: 16 independent LDGs in flight, then FMAs.
    // Output stores use streaming policy (__stcs): written once, never re-read;
    // keeps the ~54 MB output from evicting the feature footprint out of L2.
    #pragma unroll
    for (int cb = 0; cb < 16; cb += 4) {
        float v00[4], v01[4], v10[4], v11[4];
        #pragma unroll
        for (int c = 0; c < 4; ++c) {
            const float* f0 = fb + (size_t)(cb + c) * plane;
            v00[c] = __ldg(f0 + o00);
            v01[c] = __ldg(f0 + o01);
            v10[c] = __ldg(f0 + o10);
            v11[c] = __ldg(f0 + o11);
        }
        #pragma unroll
        for (int c = 0; c < 4; ++c) {
            float acc = v00[c] * w00;
            acc = fmaf(v01[c], w01, acc);
            acc = fmaf(v10[c], w10, acc);
            acc = fmaf(v11[c], w11, acc);
            __stcs(&ob[(size_t)(cb + c) * NLINES * LLEN], acc);
        }
    }
}

extern "C" void kernel_launch(void* const* d_in, const int* in_sizes, int n_in,
                              void* d_out, int out_size)
{
    const float* image   = (const float*)d_in[0];
    const float* feature = (const float*)d_in[1];
    const float* pose    = (const float*)d_in[2];
    const float* cam     = (const float*)d_in[3];
    const float* tv      = (const float*)d_in[4];
    const float* fore    = (const float*)d_in[5];
    const float* back    = (const float*)d_in[6];
    float* out = (float*)d_out;

    dim3 grid(B_ * NLINES);   // 3200 blocks, one per line
    dim3 block(256);          // 64 points x 4 channel-groups
    contour_kernel<<<grid, block>>>(image, feature, pose, cam, tv, fore, back, out);
}

// round 9
// speedup vs baseline: 1.1002x; 1.1002x over previous
#include <cuda_runtime.h>
#include <stdint.h>

// Problem constants (from reference)
#define B_      16
#define NLINES  200
#define CFEAT   64
#define HIMG    256
#define WIMG    256
#define LLEN    64
#define NBINS   32
#define EPS_    1e-5f

// Output element offsets (flattened concatenation, float32)
#define O_NORM   0
#define O_CIMG   6400
#define O_CBODY  12800
#define O_PF     22400
#define O_PB     227200
#define O_VALID  432000
#define O_AMP    435200
#define O_SLOPE  438400
#define O_FEAT   441600

// Non-contracted IEEE ops: replicate XLA's per-HLO-op rounding exactly.
__device__ __forceinline__ float mulrn(float a, float b) { return __fmul_rn(a, b); }
__device__ __forceinline__ float addrn(float a, float b) { return __fadd_rn(a, b); }
__device__ __forceinline__ float subrn(float a, float b) { return __fsub_rn(a, b); }
__device__ __forceinline__ float divrn(float a, float b) { return __fdiv_rn(a, b); }

// einsum 'bnj,bij->bni' reduction: (((0 + x0*r0) + x1*r1) + x2*r2)
__device__ __forceinline__ float dot3rn(float x0, float x1, float x2,
                                        float r0, float r1, float r2) {
    return addrn(addrn(mulrn(x0, r0), mulrn(x1, r1)), mulrn(x2, r2));
}

__global__ __launch_bounds__(256, 4)
void contour_kernel(const float* __restrict__ image,
                    const float* __restrict__ feature,
                    const float* __restrict__ pose,
                    const float* __restrict__ cam,
                    const float* __restrict__ tv,
                    const float* __restrict__ fore,
                    const float* __restrict__ back,
                    float* __restrict__ out)
{
    const int line = blockIdx.x;                 // 0 .. B*NLINES-1
    const int b = line / NLINES;
    const int n = line - b * NLINES;
    const int tid = threadIdx.x;
    const int l  = tid & (LLEN - 1);             // point index 0..63
    const int cg = tid >> 6;                     // channel group 0..3 (16 ch each)

    // ---- per-line setup ----
    const float* P = pose + b * 12;
    const float* C = cam  + b * 6;
    const float* T = tv   + (size_t)line * 8;

    const float c0 = T[0], c1 = T[1], c2 = T[2];
    const float m0 = T[3], m1 = T[4], m2 = T[5];
    const float fgd = T[6], bgd = T[7];

    const float civ0 = addrn(dot3rn(c0, c1, c2, P[0], P[1], P[2]), P[9]);
    const float civ1 = addrn(dot3rn(c0, c1, c2, P[3], P[4], P[5]), P[10]);
    const float z    = addrn(dot3rn(c0, c1, c2, P[6], P[7], P[8]), P[11]);
    const float niv0 = dot3rn(m0, m1, m2, P[0], P[1], P[2]);
    const float niv1 = dot3rn(m0, m1, m2, P[3], P[4], P[5]);

    const float sw = C[0], sh = C[1], fx = C[2], fy = C[3], ccx = C[4], ccy = C[5];

    const float zm = fmaxf(z, 1e-4f);
    const float cix = addrn(mulrn(divrn(civ0, zm), fx), ccx);
    const float ciy = addrn(mulrn(divrn(civ1, zm), fy), ccy);

    const bool valid1 = (z > 1e-4f);
    const bool inb = (cix >= 0.f) && (cix <= subrn(sw, 1.f)) &&
                     (ciy >= 0.f) && (ciy <= subrn(sh, 1.f));
    const bool cvalid = valid1 && inb;

    const float nn = __fsqrt_rn(addrn(mulrn(niv0, niv0), mulrn(niv1, niv1)));
    const float dn = fmaxf(nn, 1e-12f);
    const float nix = divrn(niv0, dn);
    const float niy = divrn(niv1, dn);

    const float curfg = divrn(mulrn(fgd, fx), z);
    const float curbg = divrn(mulrn(bgd, fx), z);
    const float cd = fminf(curfg, curbg);
    bool vdl = (cd >= 6.0f) && cvalid;

    {
        const float p0x = addrn(cix, mulrn(-31.5f, nix));
        const float p0y = addrn(ciy, mulrn(-31.5f, niy));
        const float p1x = addrn(cix, mulrn( 31.5f, nix));
        const float p1y = addrn(ciy, mulrn( 31.5f, niy));
        vdl = vdl && (p0x >= 0.f) && (p0x < 256.f) && (p0y >= 0.f) && (p0y < 256.f)
                  && (p1x >= 0.f) && (p1x < 256.f) && (p1y >= 0.f) && (p1y < 256.f);
    }

    if (tid == 0) {
        out[O_NORM  + line * 2 + 0] = nix;
        out[O_NORM  + line * 2 + 1] = niy;
        out[O_CIMG  + line * 2 + 0] = cix;
        out[O_CIMG  + line * 2 + 1] = ciy;
        out[O_CBODY + line * 3 + 0] = c0;
        out[O_CBODY + line * 3 + 1] = c1;
        out[O_CBODY + line * 3 + 2] = c2;
        out[O_VALID + line] = vdl ? 1.0f : 0.0f;
        out[O_AMP   + line] = 0.43f;
        out[O_SLOPE + line] = 0.5f;
    }

    // ---- per-point sample coordinates: exact replication (no FMA) ----
    const float step = (float)l - 31.5f;
    const float px = addrn(cix, mulrn(step, nix));
    const float py = addrn(ciy, mulrn(step, niy));

    const float gx = subrn(mulrn(divrn(px, 256.0f), 2.0f), 1.0f);
    const float gy = subrn(mulrn(divrn(py, 256.0f), 2.0f), 1.0f);
    const float xs = mulrn(subrn(mulrn(addrn(gx, 1.0f), 256.0f), 1.0f), 0.5f);
    const float ys = mulrn(subrn(mulrn(addrn(gy, 1.0f), 256.0f), 1.0f), 0.5f);

    // ---- pf/pb (nearest sample on image + histogram), cg==0 only ----
    if (cg == 0) {
        const int xi = (int)rintf(xs);     // round-half-even == jnp.round
        const int yi = (int)rintf(ys);
        const bool v = (xi >= 0) && (xi < WIMG) && (yi >= 0) && (yi < HIMG);
        const int xc = min(max(xi, 0), WIMG - 1);
        const int yc = min(max(yi, 0), HIMG - 1);
        const float* ib = image + (size_t)b * 3 * HIMG * WIMG + (size_t)yc * WIMG + xc;
        const float r  = v ? __ldg(ib)                   : 0.0f;
        const float g  = v ? __ldg(ib + HIMG * WIMG)     : 0.0f;
        const float bl = v ? __ldg(ib + 2 * HIMG * WIMG) : 0.0f;
        const int b0 = min(max((int)(r  * (float)NBINS), 0), NBINS - 1);
        const int b1 = min(max((int)(g  * (float)NBINS), 0), NBINS - 1);
        const int b2 = min(max((int)(bl * (float)NBINS), 0), NBINS - 1);
        const int hidx = (b0 * NBINS + b1) * NBINS + b2;
        float pfv = __ldg(fore + (size_t)b * NBINS * NBINS * NBINS + hidx);
        float pbv = __ldg(back + (size_t)b * NBINS * NBINS * NBINS + hidx);
        if (pfv < EPS_ && pbv < EPS_) { pfv = EPS_; pbv = EPS_; }
        const float psum = addrn(pfv, pbv);
        __stcs(&out[O_PF + (size_t)line * LLEN + l], divrn(pfv, psum));
        __stcs(&out[O_PB + (size_t)line * LLEN + l], divrn(pbv, psum));
    }

    // ---- bilinear feature sampling: 16 channels per thread ----
    const float x0f = floorf(xs);
    const float y0f = floorf(ys);
    const float wx1 = xs - x0f;
    const float wy1 = ys - y0f;
    const float wx0 = 1.0f - wx1;
    const float wy0 = 1.0f - wy1;
    const int x0 = (int)x0f, y0 = (int)y0f;
    const int x1 = x0 + 1,   y1 = y0 + 1;
    const bool vx0 = (x0 >= 0) && (x0 < WIMG);
    const bool vx1 = (x1 >= 0) && (x1 < WIMG);
    const bool vy0 = (y0 >= 0) && (y0 < HIMG);
    const bool vy1 = (y1 >= 0) && (y1 < HIMG);
    const int x0c = min(max(x0, 0), WIMG - 1);
    const int x1c = min(max(x1, 0), WIMG - 1);
    const int y0c = min(max(y0, 0), HIMG - 1);
    const int y1c = min(max(y1, 0), HIMG - 1);

    // reference accumulation order: (x0,y0), (x0,y1), (x1,y0), (x1,y1)
    const float w00 = (vx0 && vy0) ? wx0 * wy0 : 0.0f;
    const float w01 = (vx0 && vy1) ? wx0 * wy1 : 0.0f;
    const float w10 = (vx1 && vy0) ? wx1 * wy0 : 0.0f;
    const float w11 = (vx1 && vy1) ? wx1 * wy1 : 0.0f;

    // x-pair merging: one aligned float2 covers {xe, xe+1}; a second
    // (predicated) float2 covers x1 when x0c is odd and x1c != x0c.
    // All addresses provably in-bounds:
    //   xe <= 254; needb => x0c odd && x1c=x0c+1 <= 255 => x0c <= 253
    //   => pairB reads indices x0c+1, x0c+2 <= 255 (same row).
    const int  xe    = x0c & ~1;                 // even, 0..254
    const bool oddx  = (x0c & 1) != 0;
    const bool samex = (x1c == x0c);
    const bool needb = oddx && !samex;

    // float2-unit offsets (row*WIMG + xe is even)
    const int pa0 = (y0c * WIMG + xe) >> 1;      // pairA, row y0
    const int pa1 = (y1c * WIMG + xe) >> 1;      // pairA, row y1
    const int pb0 = pa0 + 1;                     // pairB, row y0
    const int pb1 = pa1 + 1;                     // pairB, row y1

    const size_t plane2 = (size_t)(HIMG * WIMG) / 2;   // plane stride in float2
    const float2* fb2 = (const float2*)feature + ((size_t)b * CFEAT + (size_t)cg * 16) * plane2;
    float* ob = out + O_FEAT + (((size_t)b * CFEAT + (size_t)cg * 16) * NLINES + n) * LLEN + l;

    // Batch 2 channels: 8 float2 loads in flight, then selects + FMAs.
    #pragma unroll
    for (int cb = 0; cb < 16; cb += 2) {
        const float2* f0 = fb2 + (size_t)cb * plane2;
        const float2* f1 = f0 + plane2;

        float2 a0c0 = __ldg(f0 + pa0);
        float2 a1c0 = __ldg(f0 + pa1);
        float2 a0c1 = __ldg(f1 + pa0);
        float2 a1c1 = __ldg(f1 + pa1);
        float2 b0c0 = make_float2(0.f, 0.f), b1c0 = b0c0, b0c1 = b0c0, b1c1 = b0c0;
        if (needb) {
            b0c0 = __ldg(f0 + pb0);
            b1c0 = __ldg(f0 + pb1);
            b0c1 = __ldg(f1 + pb0);
            b1c1 = __ldg(f1 + pb1);
        }

        // channel cb
        {
            const float v00 = oddx ? a0c0.y : a0c0.x;
            const float v01 = oddx ? a1c0.y : a1c0.x;
            const float v10 = samex ? v00 : (oddx ? b0c0.x : a0c0.y);
            const float v11 = samex ? v01 : (oddx ? b1c0.x : a1c0.y);
            float acc = v00 * w00;
            acc = fmaf(v01, w01, acc);
            acc = fmaf(v10, w10, acc);
            acc = fmaf(v11, w11, acc);
            __stcs(&ob[(size_t)cb * NLINES * LLEN], acc);
        }
        // channel cb+1
        {
            const float v00 = oddx ? a0c1.y : a0c1.x;
            const float v01 = oddx ? a1c1.y : a1c1.x;
            const float v10 = samex ? v00 : (oddx ? b0c1.x : a0c1.y);
            const float v11 = samex ? v01 : (oddx ? b1c1.x : a1c1.y);
            float acc = v00 * w00;
            acc = fmaf(v01, w01, acc);
            acc = fmaf(v10, w10, acc);
            acc = fmaf(v11, w11, acc);
            __stcs(&ob[(size_t)(cb + 1) * NLINES * LLEN], acc);
        }
    }
}

extern "C" void kernel_launch(void* const* d_in, const int* in_sizes, int n_in,
                              void* d_out, int out_size)
{
    const float* image   = (const float*)d_in[0];
    const float* feature = (const float*)d_in[1];
    const float* pose    = (const float*)d_in[2];
    const float* cam     = (const float*)d_in[3];
    const float* tv      = (const float*)d_in[4];
    const float* fore    = (const float*)d_in[5];
    const float* back    = (const float*)d_in[6];
    float* out = (float*)d_out;

    dim3 grid(B_ * NLINES);   // 3200 blocks, one per line
    dim3 block(256);          // 64 points x 4 channel-groups
    contour_kernel<<<grid, block>>>(image, feature, pose, cam, tv, fore, back, out);
}

// round 17
// speedup vs baseline: 1.1078x; 1.0069x over previous
#include <cuda_runtime.h>
#include <stdint.h>

// Problem constants (from reference)
#define B_      16
#define NLINES  200
#define CFEAT   64
#define HIMG    256
#define WIMG    256
#define LLEN    64
#define NBINS   32
#define EPS_    1e-5f

// Output element offsets (flattened concatenation, float32)
#define O_NORM   0
#define O_CIMG   6400
#define O_CBODY  12800
#define O_PF     22400
#define O_PB     227200
#define O_VALID  432000
#define O_AMP    435200
#define O_SLOPE  438400
#define O_FEAT   441600

// Non-contracted IEEE ops: replicate XLA's per-HLO-op rounding exactly.
__device__ __forceinline__ float mulrn(float a, float b) { return __fmul_rn(a, b); }
__device__ __forceinline__ float addrn(float a, float b) { return __fadd_rn(a, b); }
__device__ __forceinline__ float subrn(float a, float b) { return __fsub_rn(a, b); }
__device__ __forceinline__ float divrn(float a, float b) { return __fdiv_rn(a, b); }

// einsum 'bnj,bij->bni' reduction: (((0 + x0*r0) + x1*r1) + x2*r2)
__device__ __forceinline__ float dot3rn(float x0, float x1, float x2,
                                        float r0, float r1, float r2) {
    return addrn(addrn(mulrn(x0, r0), mulrn(x1, r1)), mulrn(x2, r2));
}

__global__ __launch_bounds__(256, 5)
void contour_kernel(const float* __restrict__ image,
                    const float* __restrict__ feature,
                    const float* __restrict__ pose,
                    const float* __restrict__ cam,
                    const float* __restrict__ tv,
                    const float* __restrict__ fore,
                    const float* __restrict__ back,
                    float* __restrict__ out)
{
    const int line = blockIdx.x;                 // 0 .. B*NLINES-1
    const int b = line / NLINES;
    const int n = line - b * NLINES;
    const int tid = threadIdx.x;
    const int l  = tid & (LLEN - 1);             // point index 0..63
    const int cg = tid >> 6;                     // channel group 0..3 (16 ch each)

    // ---- per-line setup ----
    const float* P = pose + b * 12;
    const float* C = cam  + b * 6;
    const float* T = tv   + (size_t)line * 8;

    const float c0 = T[0], c1 = T[1], c2 = T[2];
    const float m0 = T[3], m1 = T[4], m2 = T[5];
    const float fgd = T[6], bgd = T[7];

    const float civ0 = addrn(dot3rn(c0, c1, c2, P[0], P[1], P[2]), P[9]);
    const float civ1 = addrn(dot3rn(c0, c1, c2, P[3], P[4], P[5]), P[10]);
    const float z    = addrn(dot3rn(c0, c1, c2, P[6], P[7], P[8]), P[11]);
    const float niv0 = dot3rn(m0, m1, m2, P[0], P[1], P[2]);
    const float niv1 = dot3rn(m0, m1, m2, P[3], P[4], P[5]);

    const float sw = C[0], sh = C[1], fx = C[2], fy = C[3], ccx = C[4], ccy = C[5];

    const float zm = fmaxf(z, 1e-4f);
    const float cix = addrn(mulrn(divrn(civ0, zm), fx), ccx);
    const float ciy = addrn(mulrn(divrn(civ1, zm), fy), ccy);

    const bool valid1 = (z > 1e-4f);
    const bool inb = (cix >= 0.f) && (cix <= subrn(sw, 1.f)) &&
                     (ciy >= 0.f) && (ciy <= subrn(sh, 1.f));
    const bool cvalid = valid1 && inb;

    const float nn = __fsqrt_rn(addrn(mulrn(niv0, niv0), mulrn(niv1, niv1)));
    const float dn = fmaxf(nn, 1e-12f);
    const float nix = divrn(niv0, dn);
    const float niy = divrn(niv1, dn);

    const float curfg = divrn(mulrn(fgd, fx), z);
    const float curbg = divrn(mulrn(bgd, fx), z);
    const float cd = fminf(curfg, curbg);
    bool vdl = (cd >= 6.0f) && cvalid;

    {
        const float p0x = addrn(cix, mulrn(-31.5f, nix));
        const float p0y = addrn(ciy, mulrn(-31.5f, niy));
        const float p1x = addrn(cix, mulrn( 31.5f, nix));
        const float p1y = addrn(ciy, mulrn( 31.5f, niy));
        vdl = vdl && (p0x >= 0.f) && (p0x < 256.f) && (p0y >= 0.f) && (p0y < 256.f)
                  && (p1x >= 0.f) && (p1x < 256.f) && (p1y >= 0.f) && (p1y < 256.f);
    }

    if (tid == 0) {
        out[O_NORM  + line * 2 + 0] = nix;
        out[O_NORM  + line * 2 + 1] = niy;
        out[O_CIMG  + line * 2 + 0] = cix;
        out[O_CIMG  + line * 2 + 1] = ciy;
        out[O_CBODY + line * 3 + 0] = c0;
        out[O_CBODY + line * 3 + 1] = c1;
        out[O_CBODY + line * 3 + 2] = c2;
        out[O_VALID + line] = vdl ? 1.0f : 0.0f;
        out[O_AMP   + line] = 0.43f;
        out[O_SLOPE + line] = 0.5f;
    }

    // ---- per-point sample coordinates: exact replication (no FMA) ----
    const float step = (float)l - 31.5f;
    const float px = addrn(cix, mulrn(step, nix));
    const float py = addrn(ciy, mulrn(step, niy));

    const float gx = subrn(mulrn(divrn(px, 256.0f), 2.0f), 1.0f);
    const float gy = subrn(mulrn(divrn(py, 256.0f), 2.0f), 1.0f);
    const float xs = mulrn(subrn(mulrn(addrn(gx, 1.0f), 256.0f), 1.0f), 0.5f);
    const float ys = mulrn(subrn(mulrn(addrn(gy, 1.0f), 256.0f), 1.0f), 0.5f);

    // ---- pf/pb (nearest sample on image + histogram), cg==0 only ----
    if (cg == 0) {
        const int xi = (int)rintf(xs);     // round-half-even == jnp.round
        const int yi = (int)rintf(ys);
        const bool v = (xi >= 0) && (xi < WIMG) && (yi >= 0) && (yi < HIMG);
        const int xc = min(max(xi, 0), WIMG - 1);
        const int yc = min(max(yi, 0), HIMG - 1);
        const float* ib = image + (size_t)b * 3 * HIMG * WIMG + (size_t)yc * WIMG + xc;
        const float r  = v ? __ldg(ib)                   : 0.0f;
        const float g  = v ? __ldg(ib + HIMG * WIMG)     : 0.0f;
        const float bl = v ? __ldg(ib + 2 * HIMG * WIMG) : 0.0f;
        const int b0 = min(max((int)(r  * (float)NBINS), 0), NBINS - 1);
        const int b1 = min(max((int)(g  * (float)NBINS), 0), NBINS - 1);
        const int b2 = min(max((int)(bl * (float)NBINS), 0), NBINS - 1);
        const int hidx = (b0 * NBINS + b1) * NBINS + b2;
        float pfv = __ldg(fore + (size_t)b * NBINS * NBINS * NBINS + hidx);
        float pbv = __ldg(back + (size_t)b * NBINS * NBINS * NBINS + hidx);
        if (pfv < EPS_ && pbv < EPS_) { pfv = EPS_; pbv = EPS_; }
        const float psum = addrn(pfv, pbv);
        __stcs(&out[O_PF + (size_t)line * LLEN + l], divrn(pfv, psum));
        __stcs(&out[O_PB + (size_t)line * LLEN + l], divrn(pbv, psum));
    }

    // ---- bilinear feature sampling: 16 channels per thread ----
    const float x0f = floorf(xs);
    const float y0f = floorf(ys);
    const float wx1 = xs - x0f;
    const float wy1 = ys - y0f;
    const float wx0 = 1.0f - wx1;
    const float wy0 = 1.0f - wy1;
    const int x0 = (int)x0f, y0 = (int)y0f;
    const int x1 = x0 + 1,   y1 = y0 + 1;
    const bool vx0 = (x0 >= 0) && (x0 < WIMG);
    const bool vx1 = (x1 >= 0) && (x1 < WIMG);
    const bool vy0 = (y0 >= 0) && (y0 < HIMG);
    const bool vy1 = (y1 >= 0) && (y1 < HIMG);
    const int x0c = min(max(x0, 0), WIMG - 1);
    const int x1c = min(max(x1, 0), WIMG - 1);
    const int y0c = min(max(y0, 0), HIMG - 1);
    const int y1c = min(max(y1, 0), HIMG - 1);

    // reference accumulation order: (x0,y0), (x0,y1), (x1,y0), (x1,y1)
    const float w00 = (vx0 && vy0) ? wx0 * wy0 : 0.0f;
    const float w01 = (vx0 && vy1) ? wx0 * wy1 : 0.0f;
    const float w10 = (vx1 && vy0) ? wx1 * wy0 : 0.0f;
    const float w11 = (vx1 && vy1) ? wx1 * wy1 : 0.0f;

    // x-pair merging: one aligned float2 covers {xe, xe+1}; a second
    // (predicated) float2 covers x1 when x0c is odd and x1c != x0c.
    // All addresses provably in-bounds:
    //   xe <= 254; needb => x0c odd && x1c=x0c+1 <= 255 => x0c <= 253
    //   => pairB reads indices x0c+1, x0c+2 <= 255 (same row).
    const int  xe    = x0c & ~1;                 // even, 0..254
    const bool oddx  = (x0c & 1) != 0;
    const bool samex = (x1c == x0c);
    const bool needb = oddx && !samex;

    // float2-unit offsets (row*WIMG + xe is even)
    const int pa0 = (y0c * WIMG + xe) >> 1;      // pairA, row y0
    const int pa1 = (y1c * WIMG + xe) >> 1;      // pairA, row y1
    const int pb0 = pa0 + 1;                     // pairB, row y0
    const int pb1 = pa1 + 1;                     // pairB, row y1

    const size_t plane2 = (size_t)(HIMG * WIMG) / 2;   // plane stride in float2
    const float2* fb2 = (const float2*)feature + ((size_t)b * CFEAT + (size_t)cg * 16) * plane2;
    float* ob = out + O_FEAT + (((size_t)b * CFEAT + (size_t)cg * 16) * NLINES + n) * LLEN + l;

    // One channel per iteration: small live set (<= 4 float2) so the kernel
    // fits the 51-reg budget at 5 CTAs/SM. ptxas pipelines iterations as the
    // register budget allows.
    #pragma unroll
    for (int cb = 0; cb < 16; ++cb) {
        const float2* f0 = fb2 + (size_t)cb * plane2;

        float2 a0 = __ldg(f0 + pa0);
        float2 a1 = __ldg(f0 + pa1);
        float2 b0 = make_float2(0.f, 0.f), b1 = b0;
        if (needb) {
            b0 = __ldg(f0 + pb0);
            b1 = __ldg(f0 + pb1);
        }

        const float v00 = oddx ? a0.y : a0.x;
        const float v01 = oddx ? a1.y : a1.x;
        const float v10 = samex ? v00 : (oddx ? b0.x : a0.y);
        const float v11 = samex ? v01 : (oddx ? b1.x : a1.y);

        float acc = v00 * w00;
        acc = fmaf(v01, w01, acc);
        acc = fmaf(v10, w10, acc);
        acc = fmaf(v11, w11, acc);
        __stcs(&ob[(size_t)cb * NLINES * LLEN], acc);
    }
}

extern "C" void kernel_launch(void* const* d_in, const int* in_sizes, int n_in,
                              void* d_out, int out_size)
{
    const float* image   = (const float*)d_in[0];
    const float* feature = (const float*)d_in[1];
    const float* pose    = (const float*)d_in[2];
    const float* cam     = (const float*)d_in[3];
    const float* tv      = (const float*)d_in[4];
    const float* fore    = (const float*)d_in[5];
    const float* back    = (const float*)d_in[6];
    float* out = (float*)d_out;

    dim3 grid(B_ * NLINES);   // 3200 blocks, one per line
    dim3 block(256);          // 64 points x 4 channel-groups
    contour_kernel<<<grid, block>>>(image, feature, pose, cam, tv, fore, back, out);
}